// round 17
// baseline (speedup 1.0000x reference)
#include <cuda_runtime.h>
#include <cuda_fp16.h>

#define BATCH   256
#define IN_DIM  65536
#define OUT_DIM 65536

#define NB_T 2048   // transpose tiles: (IN/128) x (B/64)
#define NB_C 256
#define NB_I 512
#define PREP_SMEM 51200   // 32KB raw tile + 18KB stage

// ---------------- device scratch ----------------------------------------
__device__ float4 g_coef[OUT_DIM];                             // 1 MB
__device__ __align__(16) __half g_xth[(size_t)IN_DIM * BATCH]; // 32 MB
__device__ int    g_idx[2 * OUT_DIM];                          // 512 KB

// ---------------- fused prep: cp.async transpose + coef + idx -----------
__global__ __launch_bounds__(256) void prep_kernel(const float* __restrict__ x,
                                                   const float* __restrict__ wts,
                                                   const void*  __restrict__ idxraw) {
    extern __shared__ __align__(16) char smem_dyn[];
    float* traw = (float*)smem_dyn;                  // [64][128] f32, 32KB
    uint4* stg  = (uint4*)(smem_dyn + 32768);        // [4][32][9] uint4, 18KB
    int bx  = blockIdx.x;
    int tid = threadIdx.x;

    if (bx < NB_T) {
        int it = bx & 511, bt = bx >> 9;
        int i0 = it * 128, b0 = bt * 64;

        // ---- loads: 8x cp.async.cg 16B per thread (no LDG MSHR cap) ----
        unsigned sb = (unsigned)__cvta_generic_to_shared(traw);
        int r0  = tid >> 2;              // row (batch) 0..63
        int c16 = (tid & 3) * 8;         // first 16B-chunk of this thread
        const char* srow = (const char*)(x + (size_t)(b0 + r0) * IN_DIM + i0);
        unsigned dstb = sb + (unsigned)(r0 * 512 + c16 * 16);
        #pragma unroll
        for (int j = 0; j < 8; j++) {
            asm volatile("cp.async.cg.shared.global [%0], [%1], 16;"
                         :: "r"(dstb + j * 16), "l"(srow + (c16 + j) * 16)
                         : "memory");
        }
        asm volatile("cp.async.commit_group;" ::: "memory");
        asm volatile("cp.async.wait_group 0;" ::: "memory");
        __syncthreads();

        // ---- pack: lane l handles input col 32h+l (bank=l: conflict-free)
        int w = tid >> 5, l = tid & 31;
        #pragma unroll
        for (int h = 0; h < 4; h++) {
            float v[8];
            #pragma unroll
            for (int k = 0; k < 8; k++)
                v[k] = traw[(8 * w + k) * 128 + 32 * h + l];   // batches 8w..8w+7
            union { uint4 u; __half2 hh[4]; } pk;
            #pragma unroll
            for (int q = 0; q < 4; q++)
                pk.hh[q] = __floats2half2_rn(v[2 * q], v[2 * q + 1]);
            stg[(h * 32 + l) * 9 + w] = pk.u;    // quad (l+w)&7: conflict-free
        }
        __syncthreads();

        // ---- store: 4 rows x 128B coalesced per warp-inst ----
        #pragma unroll
        for (int h = 0; h < 4; h++) {
            int iloc = 4 * w + (l >> 3);
            int c = l & 7;
            uint4 u = stg[(h * 32 + iloc) * 9 + c];  // quad (iloc+c)&7: cf
            *(uint4*)((char*)g_xth + (size_t)(i0 + 32 * h + iloc) * 512
                      + b0 * 2 + c * 16) = u;
        }
    } else if (bx < NB_T + NB_C) {
        // softmax -> bilinear coefficients
        int o = (bx - NB_T) * 256 + tid;
        float p[16];
        const float4* w4 = (const float4*)(wts + (size_t)o * 16);
        float4 q0 = w4[0], q1 = w4[1], q2 = w4[2], q3 = w4[3];
        p[0]=q0.x; p[1]=q0.y; p[2]=q0.z; p[3]=q0.w;
        p[4]=q1.x; p[5]=q1.y; p[6]=q1.z; p[7]=q1.w;
        p[8]=q2.x; p[9]=q2.y; p[10]=q2.z; p[11]=q2.w;
        p[12]=q3.x; p[13]=q3.y; p[14]=q3.z; p[15]=q3.w;
        float m = p[0];
        #pragma unroll
        for (int i = 1; i < 16; i++) m = fmaxf(m, p[i]);
        float s = 0.f;
        #pragma unroll
        for (int i = 0; i < 16; i++) { p[i] = __expf(p[i] - m); s += p[i]; }
        float inv = 1.0f / s;
        #pragma unroll
        for (int i = 0; i < 16; i++) p[i] *= inv;
        float4 c;
        c.x = p[8]+p[9]+p[10]+p[11]+p[12]+p[13]+p[14]+p[15];
        c.y = p[2]+p[3]+p[6]+p[7]-p[8]-p[9]-p[12]-p[13];
        c.z = p[4]+p[5]+p[6]+p[7]-p[8]-p[9]-p[10]-p[11];
        c.w = p[1]-p[2]-p[4]-2.f*p[6]-p[7]+p[8]+2.f*p[9]+p[11]+p[13]-p[14];
        g_coef[o] = c;
    } else {
        __shared__ int s64;
        if (tid == 0) {
            const long long* p = (const long long*)idxraw;
            int is64 = 1;
            #pragma unroll 1
            for (int j = 0; j < 64; j++) {
                long long vv = p[j];
                if (vv < 0 || vv >= IN_DIM) { is64 = 0; break; }
            }
            s64 = is64;
        }
        __syncthreads();
        int i = (bx - NB_T - NB_C) * 256 + tid;
        g_idx[i] = s64 ? (int)((const long long*)idxraw)[i]
                       : ((const int*)idxraw)[i];
    }
}

// ---------------- main: 128-bit staged, 8 warps x 4 neurons (R14) -------
__global__ __launch_bounds__(256, 3) void logic_main_kernel(float* __restrict__ out) {
    __shared__ __align__(16) float s[BATCH * 32];   // 32 KB
    int tid = threadIdx.x;
    int w = tid >> 5;
    int l = tid & 31;
    int ob = blockIdx.x * 32;
    int n0 = w * 4;

    int ia[4], ib[4];
    #pragma unroll
    for (int c = 0; c < 4; c++) {
        int o = ob + n0 + c;
        ia[c] = g_idx[o];
        ib[c] = g_idx[OUT_DIM + o];
    }
    uint4 va[4], vb[4];
    #pragma unroll
    for (int c = 0; c < 4; c++) {
        va[c] = ((const uint4*)(g_xth + (size_t)ia[c] * BATCH))[l];
        vb[c] = ((const uint4*)(g_xth + (size_t)ib[c] * BATCH))[l];
    }
    float4 cf[4];
    #pragma unroll
    for (int c = 0; c < 4; c++) cf[c] = g_coef[ob + n0 + c];

    int colq4 = 4 * ((w + l) & 7);
    #pragma unroll
    for (int k = 0; k < 8; k++) {
        float v[4];
        #pragma unroll
        for (int c = 0; c < 4; c++) {
            const __half2* Ah = (const __half2*)&va[c];
            const __half2* Bh = (const __half2*)&vb[c];
            float2 a2 = __half22float2(Ah[k >> 1]);
            float2 b2 = __half22float2(Bh[k >> 1]);
            float a = (k & 1) ? a2.y : a2.x;
            float b = (k & 1) ? b2.y : b2.x;
            v[c] = fmaf(fmaf(cf[c].w, b, cf[c].y), a, fmaf(cf[c].z, b, cf[c].x));
        }
        *(float4*)&s[(8 * l + k) * 32 + colq4] = make_float4(v[0], v[1], v[2], v[3]);
    }
    __syncthreads();

    int q = l & 7;
    int rsub = l >> 3;
    #pragma unroll
    for (int g = 0; g < 8; g++) {
        int row = w * 32 + 4 * g + rsub;
        int c4 = (q + (row >> 3)) & 7;
        float4 val = *(const float4*)&s[row * 32 + 4 * c4];
        __stcs((float4*)(out + (size_t)row * OUT_DIM + ob + 4 * q), val);
    }
}

// ---------------- launch ------------------------------------------------
extern "C" void kernel_launch(void* const* d_in, const int* in_sizes, int n_in,
                              void* d_out, int out_size) {
    const float* x   = (const float*)d_in[0];
    const float* wts = (const float*)d_in[1];
    const void*  idx = d_in[2];
    float* out = (float*)d_out;

    static int smem_set = 0;
    if (!smem_set) {
        cudaFuncSetAttribute(prep_kernel,
                             cudaFuncAttributeMaxDynamicSharedMemorySize, PREP_SMEM);
        smem_set = 1;
    }

    prep_kernel<<<NB_T + NB_C + NB_I, 256, PREP_SMEM>>>(x, wts, idx);
    logic_main_kernel<<<OUT_DIM / 32, 256>>>(out);
}